// round 8
// baseline (speedup 1.0000x reference)
#include <cuda_runtime.h>
#include <cuda_bf16.h>
#include <math.h>
#include <stdint.h>

#define N_PTS 8192
#define D_DIM 256
#define NUM_CLS 64
#define EPSF  1e-10f

#define BT 128                    // CTA tile M = N
#define BKE 64                    // K chunk in bf16 elems = 128 B per row
#define NCHUNK (D_DIM / BKE)      // 4
#define NSTAGE 2
#define ROWB 144                  // padded row stride in bytes (72 bf16)
#define STAGE_BYTES (256 * ROWB)  // A rows 0-127, B rows 128-255
#define AUX_OFF (NSTAGE * STAGE_BYTES)
#define SMEM_TOTAL (AUX_OFF + 4 * BT * 4)
#define N_TILES (N_PTS / BT)      // 64
#define N_CTAS (N_TILES * (N_TILES + 1) / 2)  // 2080

__device__ float g_sq[N_PTS];
__device__ float g_pos[N_PTS];
__device__ float g_neg[N_PTS];
__device__ int   g_cls[N_PTS];
__device__ int   g_done = 0;
__device__ __nv_bfloat16 g_bf[N_PTS * D_DIM];   // bf16 copy of pred

static __device__ __forceinline__ uint32_t smem_u32(const void* p) {
    uint32_t a;
    asm("{ .reg .u64 t; cvta.to.shared.u64 t, %1; cvt.u32.u64 %0, t; }"
        : "=r"(a) : "l"(p));
    return a;
}
static __device__ __forceinline__ void cp16(uint32_t dst, const void* src) {
    asm volatile("cp.async.cg.shared.global [%0], [%1], 16;"
                 :: "r"(dst), "l"(src) : "memory");
}
#define CP_COMMIT() asm volatile("cp.async.commit_group;" ::: "memory")
#define CP_WAIT0()  asm volatile("cp.async.wait_group 0;" ::: "memory")

static __device__ __forceinline__ void ldsm4(uint32_t* r, uint32_t addr) {
    asm volatile("ldmatrix.sync.aligned.m8n8.x4.shared.b16 {%0,%1,%2,%3}, [%4];"
                 : "=r"(r[0]), "=r"(r[1]), "=r"(r[2]), "=r"(r[3]) : "r"(addr));
}
static __device__ __forceinline__ void mma_bf16(float* c, const uint32_t* a,
                                                const uint32_t* b) {
    asm volatile(
        "mma.sync.aligned.m16n8k16.row.col.f32.bf16.bf16.f32 "
        "{%0,%1,%2,%3}, {%4,%5,%6,%7}, {%8,%9}, {%0,%1,%2,%3};"
        : "+f"(c[0]), "+f"(c[1]), "+f"(c[2]), "+f"(c[3])
        : "r"(a[0]), "r"(a[1]), "r"(a[2]), "r"(a[3]), "r"(b[0]), "r"(b[1]));
}

// ---------------------------------------------------------------------------
// Kernel 1: squared norms (exact fp32) + bf16 conversion + dtype detect +
// class load + accumulator zero. One warp per row.
// ---------------------------------------------------------------------------
__global__ void prep_kernel(const float* __restrict__ pred,
                            const void* __restrict__ tgt) {
    int warp = (blockIdx.x * blockDim.x + threadIdx.x) >> 5;
    int lane = threadIdx.x & 31;
    if (warp >= N_PTS) return;

    // dtype scan on first 1KB (L2-resident): int32 data shows values >= 64
    const long long* t64 = (const long long*)tgt;
    int bad = 0;
#pragma unroll
    for (int q = 0; q < 4; ++q) {
        long long v = t64[lane + 32 * q];
        bad |= (v < 0 || v >= (long long)NUM_CLS);
    }
    bool is64 = (__ballot_sync(0xffffffffu, bad) == 0u);

    const float4* row = (const float4*)(pred + (size_t)warp * D_DIM);
    float s = 0.f;
#pragma unroll
    for (int q = 0; q < 2; ++q) {
        float4 v = row[lane + 32 * q];
        s += v.x * v.x + v.y * v.y + v.z * v.z + v.w * v.w;
        __nv_bfloat162 p0 = __float22bfloat162_rn(make_float2(v.x, v.y));
        __nv_bfloat162 p1 = __float22bfloat162_rn(make_float2(v.z, v.w));
        uint2 u;
        u.x = *(uint32_t*)&p0; u.y = *(uint32_t*)&p1;
        *(uint2*)(g_bf + (size_t)warp * D_DIM + 4 * (lane + 32 * q)) = u;
    }
#pragma unroll
    for (int o = 16; o; o >>= 1) s += __shfl_xor_sync(0xffffffffu, s, o);
    if (lane == 0) {
        g_sq[warp]  = s;
        g_pos[warp] = 0.f;
        g_neg[warp] = 0.f;
        g_cls[warp] = is64 ? (int)t64[warp] : ((const int*)tgt)[warp];
    }
}

// ---------------------------------------------------------------------------
// Kernel 2: bf16 m16n8k16 Gram tile, 4 fat warps (64x64 warp tile),
// double-buffered cp.async, fused epilogue + folded finalize.
// ---------------------------------------------------------------------------
__global__ __launch_bounds__(128, 2)
void tile_kernel(const float* __restrict__ tempPtr,
                 float* __restrict__ out) {
    // decode triangular index t -> (bi, bj), bi <= bj
    int t = blockIdx.x;
    int bi = (int)((129.0f - sqrtf(16641.0f - 8.0f * (float)t)) * 0.5f);
    while ((bi + 1) * (129 - (bi + 1)) / 2 <= t) ++bi;
    while (bi * (129 - bi) / 2 > t) --bi;
    int bj = bi + (t - bi * (129 - bi) / 2);

    extern __shared__ char smc[];
    uint32_t sbase = smem_u32(smc);
    float* sqR = (float*)(smc + AUX_OFF);
    float* sqC = sqR + BT;
    int*   clR = (int*)(sqC + BT);
    int*   clC = clR + BT;

    int tid  = threadIdx.x;
    int lane = tid & 31, wid = tid >> 5;
    int wm = wid & 1, wn = wid >> 1;              // 2 x 2 warp grid
    int R0 = wm * 64, C0 = wn * 64;
    int gq = lane >> 2, tq = lane & 3;
    int i0 = bi * BT, j0 = bj * BT;

    if (tid < BT) {
        sqR[tid] = g_sq[i0 + tid];
        sqC[tid] = g_sq[j0 + tid];
        clR[tid] = g_cls[i0 + tid];
        clC[tid] = g_cls[j0 + tid];
    }

    // per-thread cp.async role: 16 x 16B per chunk
    int seg = tid & 7;                            // 16B segment within 128B
    int rbase = tid >> 3;                         // 0..15
    const __nv_bfloat16* srcA = g_bf + (size_t)i0 * D_DIM;
    const __nv_bfloat16* srcB = g_bf + (size_t)j0 * D_DIM;

    auto issue = [&](int stage, int k0) {
        uint32_t sdst = sbase + (uint32_t)(stage * STAGE_BYTES) + seg * 16u;
#pragma unroll
        for (int i = 0; i < 16; ++i) {
            int row = rbase + 16 * i;             // 0..255
            const __nv_bfloat16* src = (row < 128)
                ? srcA + (size_t)row * D_DIM
                : srcB + (size_t)(row - 128) * D_DIM;
            cp16(sdst + (uint32_t)row * ROWB, src + k0 + seg * 8);
        }
        CP_COMMIT();
    };

    uint32_t offA = (uint32_t)((R0 + (lane & 15)) * ROWB + (lane >> 4) * 16);
    uint32_t offB = (uint32_t)((128 + C0 + (lane >> 4) * 8 + (lane & 7)) * ROWB
                               + ((lane >> 3) & 1) * 16);

    float acc[4][8][4];
#pragma unroll
    for (int mi = 0; mi < 4; mi++)
#pragma unroll
        for (int ni = 0; ni < 8; ni++)
#pragma unroll
            for (int v = 0; v < 4; v++) acc[mi][ni][v] = 0.f;

    issue(0, 0);
#pragma unroll 1
    for (int c = 0; c < NCHUNK; ++c) {
        CP_WAIT0();                               // chunk c landed
        __syncthreads();                          // + all warps done with c-1
        if (c + 1 < NCHUNK) issue((c + 1) & 1, (c + 1) * BKE);

        uint32_t sA = sbase + (uint32_t)((c & 1) * STAGE_BYTES);
#pragma unroll
        for (int ks = 0; ks < 4; ++ks) {          // k16 steps within 64-chunk
            uint32_t a[4][4], b[8][2];
#pragma unroll
            for (int mi = 0; mi < 4; mi++)
                ldsm4(a[mi], sA + offA + (uint32_t)(mi * 16 * ROWB + ks * 32));
#pragma unroll
            for (int p = 0; p < 4; p++) {
                uint32_t r[4];
                ldsm4(r, sA + offB + (uint32_t)(p * 16 * ROWB + ks * 32));
                b[2 * p][0] = r[0]; b[2 * p][1] = r[1];
                b[2 * p + 1][0] = r[2]; b[2 * p + 1][1] = r[3];
            }
#pragma unroll
            for (int mi = 0; mi < 4; mi++)
#pragma unroll
                for (int ni = 0; ni < 8; ni++)
                    mma_bf16(acc[mi][ni], a[mi], b[ni]);
        }
    }

    // ---- Epilogue: exp + masked sums on register fragments ----
    float invT = 1.0f / tempPtr[0];
    bool diag  = (bi == bj);

    float rP[8], rN[8], cP[16], cN[16];
#pragma unroll
    for (int q = 0; q < 8; q++)  { rP[q] = rN[q] = 0.f; }
#pragma unroll
    for (int q = 0; q < 16; q++) { cP[q] = cN[q] = 0.f; }

#pragma unroll
    for (int mi = 0; mi < 4; mi++)
#pragma unroll
        for (int h = 0; h < 2; h++) {
            int rl = R0 + mi * 16 + gq + h * 8;
            float sqi = sqR[rl];
            int   ci  = clR[rl];
#pragma unroll
            for (int ni = 0; ni < 8; ni++)
#pragma unroll
                for (int w = 0; w < 2; w++) {
                    int cl = C0 + ni * 8 + tq * 2 + w;
                    float dot = acc[mi][ni][h * 2 + w];
                    float pn  = fmaxf(sqi + sqC[cl] - 2.0f * dot, EPSF);
                    float dv  = __expf(-pn * invT);
                    if (diag && rl == cl) dv = 0.f;
                    bool same = (ci == clC[cl]);
                    float p = same ? dv : 0.f;
                    float n = dv - p;
                    rP[mi * 2 + h] += p; rN[mi * 2 + h] += n;
                    cP[ni * 2 + w] += p; cN[ni * 2 + w] += n;
                }
        }

#pragma unroll
    for (int q = 0; q < 16; q++) {
#pragma unroll
        for (int o = 4; o <= 16; o <<= 1) {
            cP[q] += __shfl_xor_sync(0xffffffffu, cP[q], o);
            cN[q] += __shfl_xor_sync(0xffffffffu, cN[q], o);
        }
    }
    if (lane < 4) {
#pragma unroll
        for (int q = 0; q < 16; q++) {
            int cl = C0 + (q >> 1) * 8 + lane * 2 + (q & 1);
            atomicAdd(&g_pos[j0 + cl], cP[q]);
            atomicAdd(&g_neg[j0 + cl], cN[q]);
        }
    }
#pragma unroll
    for (int q = 0; q < 8; q++) {
#pragma unroll
        for (int o = 1; o <= 2; o <<= 1) {
            rP[q] += __shfl_xor_sync(0xffffffffu, rP[q], o);
            rN[q] += __shfl_xor_sync(0xffffffffu, rN[q], o);
        }
    }
    if (!diag && tq == 0) {
#pragma unroll
        for (int q = 0; q < 8; q++) {
            int rl = R0 + (q >> 1) * 16 + gq + (q & 1) * 8;
            atomicAdd(&g_pos[i0 + rl], rP[q]);
            atomicAdd(&g_neg[i0 + rl], rN[q]);
        }
    }

    // ---- Folded finalize: last CTA to finish reduces the loss ----
    __shared__ int s_last;
    __syncthreads();
    if (tid == 0) {
        __threadfence();
        s_last = (atomicAdd(&g_done, 1) == N_CTAS - 1);
    }
    __syncthreads();
    if (s_last) {
        __threadfence();
        __shared__ float red[4];
        float s = 0.f;
        for (int j = tid; j < N_PTS; j += 128) {
            float num = g_pos[j];
            float den = fmaxf(g_neg[j], EPSF);
            float frac = num / (num + den);
            if (frac >= EPSF) s += logf(frac);
        }
#pragma unroll
        for (int o = 16; o; o >>= 1) s += __shfl_xor_sync(0xffffffffu, s, o);
        if (lane == 0) red[wid] = s;
        __syncthreads();
        if (tid == 0) {
            out[0] = -(red[0] + red[1] + red[2] + red[3]) / (float)N_PTS;
            g_done = 0;   // reset for deterministic graph replay
        }
    }
}

// ---------------------------------------------------------------------------
extern "C" void kernel_launch(void* const* d_in, const int* in_sizes, int n_in,
                              void* d_out, int out_size) {
    const float* pred = (const float*)d_in[0];
    const void*  tgt  = d_in[1];
    const float* temp = (const float*)d_in[2];

    cudaFuncSetAttribute(tile_kernel,
                         cudaFuncAttributeMaxDynamicSharedMemorySize, SMEM_TOTAL);

    prep_kernel<<<(N_PTS * 32 + 255) / 256, 256>>>(pred, tgt);
    tile_kernel<<<N_CTAS, 128, SMEM_TOTAL>>>(temp, (float*)d_out);
}

// round 10
// speedup vs baseline: 1.4625x; 1.4625x over previous
#include <cuda_runtime.h>
#include <math.h>
#include <stdint.h>

#define N_PTS 8192
#define D_DIM 256
#define NUM_CLS 64
#define EPSF  1e-10f

#define BT 128                    // CTA tile M = N
#define CE 128                    // K chunk in int8 elems = 128 B per row
#define NCHUNK (D_DIM / CE)       // 2
#define NSTAGE 2
#define ROWB 144                  // padded row stride in bytes (128 + 16)
#define STAGE_BYTES (256 * ROWB)  // A rows 0-127, B rows 128-255
#define AUX_OFF (NSTAGE * STAGE_BYTES)
#define SMEM_TOTAL (AUX_OFF + 6 * BT * 4)
#define N_TILES (N_PTS / BT)      // 64
#define N_CTAS (N_TILES * (N_TILES + 1) / 2)  // 2080

__device__ float    g_sq[N_PTS];
__device__ float    g_rs[N_PTS];            // reciprocal scale = max|x|/127
__device__ float    g_pos[N_PTS];
__device__ float    g_neg[N_PTS];
__device__ int      g_cls[N_PTS];
__device__ int      g_done = 0;
__device__ uint32_t g_q8[N_PTS * (D_DIM / 4)];   // packed int8 rows (256B each)

static __device__ __forceinline__ uint32_t smem_u32(const void* p) {
    uint32_t a;
    asm("{ .reg .u64 t; cvta.to.shared.u64 t, %1; cvt.u32.u64 %0, t; }"
        : "=r"(a) : "l"(p));
    return a;
}
static __device__ __forceinline__ void cp16(uint32_t dst, const void* src) {
    asm volatile("cp.async.cg.shared.global [%0], [%1], 16;"
                 :: "r"(dst), "l"(src) : "memory");
}
#define CP_COMMIT() asm volatile("cp.async.commit_group;" ::: "memory")
#define CP_WAIT(n)  asm volatile("cp.async.wait_group %0;" :: "n"(n) : "memory")

static __device__ __forceinline__ void ldsm4(uint32_t* r, uint32_t addr) {
    asm volatile("ldmatrix.sync.aligned.m8n8.x4.shared.b16 {%0,%1,%2,%3}, [%4];"
                 : "=r"(r[0]), "=r"(r[1]), "=r"(r[2]), "=r"(r[3]) : "r"(addr));
}
static __device__ __forceinline__ void mma_s8(int* c, const uint32_t* a,
                                              const uint32_t* b) {
    asm volatile(
        "mma.sync.aligned.m16n8k32.row.col.s32.s8.s8.s32 "
        "{%0,%1,%2,%3}, {%4,%5,%6,%7}, {%8,%9}, {%0,%1,%2,%3};"
        : "+r"(c[0]), "+r"(c[1]), "+r"(c[2]), "+r"(c[3])
        : "r"(a[0]), "r"(a[1]), "r"(a[2]), "r"(a[3]), "r"(b[0]), "r"(b[1]));
}
static __device__ __forceinline__ uint32_t pack4(float4 v, float s) {
    int q0 = __float2int_rn(v.x * s), q1 = __float2int_rn(v.y * s);
    int q2 = __float2int_rn(v.z * s), q3 = __float2int_rn(v.w * s);
    return (uint32_t)(q0 & 255) | ((uint32_t)(q1 & 255) << 8) |
           ((uint32_t)(q2 & 255) << 16) | ((uint32_t)(q3 & 255) << 24);
}

// ---------------------------------------------------------------------------
// Kernel 1: per-row squared norm (exact fp32), per-row int8 quantization with
// symmetric scale, dtype detect, class load, accumulator zero. One warp/row.
// ---------------------------------------------------------------------------
__global__ void prep_kernel(const float* __restrict__ pred,
                            const void* __restrict__ tgt) {
    int warp = (blockIdx.x * blockDim.x + threadIdx.x) >> 5;
    int lane = threadIdx.x & 31;
    if (warp >= N_PTS) return;

    // dtype scan on first 1KB (L2-resident): int32 data shows values >= 64
    const long long* t64 = (const long long*)tgt;
    int bad = 0;
#pragma unroll
    for (int q = 0; q < 4; ++q) {
        long long v = t64[lane + 32 * q];
        bad |= (v < 0 || v >= (long long)NUM_CLS);
    }
    bool is64 = (__ballot_sync(0xffffffffu, bad) == 0u);

    const float4* row = (const float4*)(pred + (size_t)warp * D_DIM);
    float4 v0 = row[lane], v1 = row[lane + 32];
    float s = v0.x * v0.x + v0.y * v0.y + v0.z * v0.z + v0.w * v0.w
            + v1.x * v1.x + v1.y * v1.y + v1.z * v1.z + v1.w * v1.w;
    float m = fmaxf(fmaxf(fmaxf(fabsf(v0.x), fabsf(v0.y)),
                          fmaxf(fabsf(v0.z), fabsf(v0.w))),
                    fmaxf(fmaxf(fabsf(v1.x), fabsf(v1.y)),
                          fmaxf(fabsf(v1.z), fabsf(v1.w))));
#pragma unroll
    for (int o = 16; o; o >>= 1) {
        s += __shfl_xor_sync(0xffffffffu, s, o);
        m = fmaxf(m, __shfl_xor_sync(0xffffffffu, m, o));
    }
    float scale = 127.0f / m;                    // m > 0 for gaussian data
    g_q8[warp * 64 + lane]      = pack4(v0, scale);
    g_q8[warp * 64 + 32 + lane] = pack4(v1, scale);
    if (lane == 0) {
        g_sq[warp]  = s;
        g_rs[warp]  = m * (1.0f / 127.0f);
        g_pos[warp] = 0.f;
        g_neg[warp] = 0.f;
        g_cls[warp] = is64 ? (int)t64[warp] : ((const int*)tgt)[warp];
    }
}

// ---------------------------------------------------------------------------
// Kernel 2: int8 m16n8k32 Gram tile (8 warps, 64x32 warp tiles), both K
// chunks prefetched up-front, fused fp32 epilogue + folded finalize.
// ---------------------------------------------------------------------------
__global__ __launch_bounds__(256, 2)
void tile_kernel(const float* __restrict__ tempPtr,
                 float* __restrict__ out) {
    // decode triangular index t -> (bi, bj), bi <= bj
    int t = blockIdx.x;
    int bi = (int)((129.0f - sqrtf(16641.0f - 8.0f * (float)t)) * 0.5f);
    while ((bi + 1) * (129 - (bi + 1)) / 2 <= t) ++bi;
    while (bi * (129 - bi) / 2 > t) --bi;
    int bj = bi + (t - bi * (129 - bi) / 2);

    extern __shared__ char smc[];
    uint32_t sbase = smem_u32(smc);
    float* sqR = (float*)(smc + AUX_OFF);
    float* sqC = sqR + BT;
    float* rsR = sqC + BT;
    float* rsC = rsR + BT;
    int*   clR = (int*)(rsC + BT);
    int*   clC = clR + BT;

    int tid  = threadIdx.x;
    int lane = tid & 31, wid = tid >> 5;
    int wm = wid & 1, wn = wid >> 1;              // 2 x 4 warp grid
    int R0 = wm * 64, C0 = wn * 32;
    int gq = lane >> 2, tq = lane & 3;
    int i0 = bi * BT, j0 = bj * BT;

    if (tid < BT) {
        sqR[tid] = g_sq[i0 + tid];
        sqC[tid] = g_sq[j0 + tid];
        rsR[tid] = g_rs[i0 + tid];
        rsC[tid] = g_rs[j0 + tid];
        clR[tid] = g_cls[i0 + tid];
        clC[tid] = g_cls[j0 + tid];
    }

    // per-thread cp.async role: 8 x 16B per chunk (256 rows x 128B)
    int seg = tid & 7;                            // 16B segment within 128B
    int rbase = tid >> 3;                         // 0..31
    const char* srcA = (const char*)g_q8 + (size_t)i0 * D_DIM;
    const char* srcB = (const char*)g_q8 + (size_t)j0 * D_DIM;

    auto issue = [&](int stage, int k0) {
        uint32_t sdst = sbase + (uint32_t)(stage * STAGE_BYTES) + seg * 16u;
#pragma unroll
        for (int i = 0; i < 8; ++i) {
            int row = rbase + 32 * i;             // 0..255
            const char* src = (row < 128)
                ? srcA + (size_t)row * D_DIM
                : srcB + (size_t)(row - 128) * D_DIM;
            cp16(sdst + (uint32_t)row * ROWB, src + k0 + seg * 16);
        }
        CP_COMMIT();
    };

    // ldmatrix byte offsets (16B halves of each 32B k-step)
    uint32_t offA = (uint32_t)((R0 + (lane & 15)) * ROWB + (lane >> 4) * 16);
    uint32_t offB = (uint32_t)((128 + C0 + (lane >> 4) * 8 + (lane & 7)) * ROWB
                               + ((lane >> 3) & 1) * 16);

    int acc[4][4][4];
#pragma unroll
    for (int mi = 0; mi < 4; mi++)
#pragma unroll
        for (int ni = 0; ni < 4; ni++)
#pragma unroll
            for (int v = 0; v < 4; v++) acc[mi][ni][v] = 0;

    issue(0, 0);                                  // chunk 0: k bytes [0,128)
    issue(1, CE);                                 // chunk 1: k bytes [128,256)
#pragma unroll 1
    for (int c = 0; c < NCHUNK; ++c) {
        if (c == 0) CP_WAIT(1); else CP_WAIT(0);
        __syncthreads();

        uint32_t sA = sbase + (uint32_t)(c * STAGE_BYTES);
#pragma unroll
        for (int ks = 0; ks < 4; ++ks) {          // k32 steps within 128B
            uint32_t a[4][4], b[4][2];
#pragma unroll
            for (int mi = 0; mi < 4; mi++)
                ldsm4(a[mi], sA + offA + (uint32_t)(mi * 16 * ROWB + ks * 32));
#pragma unroll
            for (int p = 0; p < 2; p++) {
                uint32_t r[4];
                ldsm4(r, sA + offB + (uint32_t)(p * 16 * ROWB + ks * 32));
                b[2 * p][0] = r[0]; b[2 * p][1] = r[1];
                b[2 * p + 1][0] = r[2]; b[2 * p + 1][1] = r[3];
            }
#pragma unroll
            for (int mi = 0; mi < 4; mi++)
#pragma unroll
                for (int ni = 0; ni < 4; ni++)
                    mma_s8(acc[mi][ni], a[mi], b[ni]);
        }
    }

    // ---- Epilogue: dequant + exp + masked sums on register fragments ----
    float invT = 1.0f / tempPtr[0];
    bool diag  = (bi == bj);

    // hoist per-thread row/col constants
    float sqi_r[8], rsi_r[8]; int ci_r[8];
#pragma unroll
    for (int q = 0; q < 8; q++) {
        int rl = R0 + (q >> 1) * 16 + gq + (q & 1) * 8;
        sqi_r[q] = sqR[rl]; rsi_r[q] = rsR[rl]; ci_r[q] = clR[rl];
    }
    float sqj_r[8], rsj_r[8]; int cj_r[8];
#pragma unroll
    for (int q = 0; q < 8; q++) {
        int cl = C0 + (q >> 1) * 8 + tq * 2 + (q & 1);
        sqj_r[q] = sqC[cl]; rsj_r[q] = rsC[cl]; cj_r[q] = clC[cl];
    }

    float rP[8], rN[8], cP[8], cN[8];
#pragma unroll
    for (int q = 0; q < 8; q++) { rP[q] = rN[q] = cP[q] = cN[q] = 0.f; }

#pragma unroll
    for (int mi = 0; mi < 4; mi++)
#pragma unroll
        for (int h = 0; h < 2; h++) {
            int qr = mi * 2 + h;
            int rl = R0 + mi * 16 + gq + h * 8;
#pragma unroll
            for (int ni = 0; ni < 4; ni++)
#pragma unroll
                for (int w = 0; w < 2; w++) {
                    int qc = ni * 2 + w;
                    int cl = C0 + ni * 8 + tq * 2 + w;
                    float dot = (float)acc[mi][ni][h * 2 + w]
                                * (rsi_r[qr] * rsj_r[qc]);
                    float pn  = fmaxf(sqi_r[qr] + sqj_r[qc] - 2.0f * dot, EPSF);
                    float dv  = __expf(-pn * invT);
                    if (diag && rl == cl) dv = 0.f;
                    bool same = (ci_r[qr] == cj_r[qc]);
                    float p = same ? dv : 0.f;
                    float n = dv - p;
                    rP[qr] += p; rN[qr] += n;
                    cP[qc] += p; cN[qc] += n;
                }
        }

#pragma unroll
    for (int q = 0; q < 8; q++) {
#pragma unroll
        for (int o = 4; o <= 16; o <<= 1) {
            cP[q] += __shfl_xor_sync(0xffffffffu, cP[q], o);
            cN[q] += __shfl_xor_sync(0xffffffffu, cN[q], o);
        }
    }
    if (lane < 4) {
#pragma unroll
        for (int q = 0; q < 8; q++) {
            int cl = C0 + (q >> 1) * 8 + lane * 2 + (q & 1);
            atomicAdd(&g_pos[j0 + cl], cP[q]);
            atomicAdd(&g_neg[j0 + cl], cN[q]);
        }
    }
#pragma unroll
    for (int q = 0; q < 8; q++) {
#pragma unroll
        for (int o = 1; o <= 2; o <<= 1) {
            rP[q] += __shfl_xor_sync(0xffffffffu, rP[q], o);
            rN[q] += __shfl_xor_sync(0xffffffffu, rN[q], o);
        }
    }
    if (!diag && tq == 0) {
#pragma unroll
        for (int q = 0; q < 8; q++) {
            int rl = R0 + (q >> 1) * 16 + gq + (q & 1) * 8;
            atomicAdd(&g_pos[i0 + rl], rP[q]);
            atomicAdd(&g_neg[i0 + rl], rN[q]);
        }
    }

    // ---- Folded finalize: last CTA to finish reduces the loss ----
    __shared__ int s_last;
    __syncthreads();
    if (tid == 0) {
        __threadfence();
        s_last = (atomicAdd(&g_done, 1) == N_CTAS - 1);
    }
    __syncthreads();
    if (s_last) {
        __threadfence();
        __shared__ float red[8];
        float s = 0.f;
        for (int j = tid; j < N_PTS; j += 256) {
            float num = g_pos[j];
            float den = fmaxf(g_neg[j], EPSF);
            float frac = num / (num + den);
            if (frac >= EPSF) s += logf(frac);
        }
#pragma unroll
        for (int o = 16; o; o >>= 1) s += __shfl_xor_sync(0xffffffffu, s, o);
        if (lane == 0) red[wid] = s;
        __syncthreads();
        if (tid < 8) {
            float v = red[tid];
#pragma unroll
            for (int o = 4; o; o >>= 1) v += __shfl_xor_sync(0xffu, v, o);
            if (tid == 0) {
                out[0] = -v / (float)N_PTS;
                g_done = 0;   // reset for deterministic graph replay
            }
        }
    }
}

// ---------------------------------------------------------------------------
extern "C" void kernel_launch(void* const* d_in, const int* in_sizes, int n_in,
                              void* d_out, int out_size) {
    const float* pred = (const float*)d_in[0];
    const void*  tgt  = d_in[1];
    const float* temp = (const float*)d_in[2];

    cudaFuncSetAttribute(tile_kernel,
                         cudaFuncAttributeMaxDynamicSharedMemorySize, SMEM_TOTAL);

    prep_kernel<<<(N_PTS * 32 + 255) / 256, 256>>>(pred, tgt);
    tile_kernel<<<N_CTAS, 256, SMEM_TOTAL>>>(temp, (float*)d_out);
}

// round 11
// speedup vs baseline: 1.5753x; 1.0771x over previous
#include <cuda_runtime.h>
#include <math.h>
#include <stdint.h>

#define N_PTS 8192
#define D_DIM 256
#define NUM_CLS 64
#define EPSF  1e-10f
#define LOG2E 1.4426950408889634f

#define BT 128                    // tile M = N
#define CE 128                    // K chunk in int8 elems = 128 B per row
#define ROWB 144                  // padded row stride in bytes (128 + 16)
#define STAGE_BYTES (256 * ROWB)  // A rows 0-127, B rows 128-255
#define AUX_OFF (2 * STAGE_BYTES)
#define SMEM_TOTAL (AUX_OFF + 6 * BT * 4)
#define N_TILES (N_PTS / BT)      // 64
#define N_CTAS (N_TILES * (N_TILES + 1) / 2)  // 2080
#define GRID_P 296                // persistent CTAs (2 per SM x 148)

__device__ float4   g_aux[N_PTS];           // {b, rk, cls(bits), 0}
__device__ float    g_pos[N_PTS];
__device__ float    g_neg[N_PTS];
__device__ int      g_work;
__device__ int      g_done;
__device__ uint32_t g_q8[N_PTS * (D_DIM / 4)];   // packed int8 rows (256B)

static __device__ __forceinline__ uint32_t smem_u32(const void* p) {
    uint32_t a;
    asm("{ .reg .u64 t; cvta.to.shared.u64 t, %1; cvt.u32.u64 %0, t; }"
        : "=r"(a) : "l"(p));
    return a;
}
static __device__ __forceinline__ void cp16(uint32_t dst, const void* src) {
    asm volatile("cp.async.cg.shared.global [%0], [%1], 16;"
                 :: "r"(dst), "l"(src) : "memory");
}
#define CP_COMMIT() asm volatile("cp.async.commit_group;" ::: "memory")
#define CP_WAIT(n)  asm volatile("cp.async.wait_group %0;" :: "n"(n) : "memory")

static __device__ __forceinline__ void ldsm4(uint32_t* r, uint32_t addr) {
    asm volatile("ldmatrix.sync.aligned.m8n8.x4.shared.b16 {%0,%1,%2,%3}, [%4];"
                 : "=r"(r[0]), "=r"(r[1]), "=r"(r[2]), "=r"(r[3]) : "r"(addr));
}
static __device__ __forceinline__ void mma_s8(int* c, const uint32_t* a,
                                              const uint32_t* b) {
    asm volatile(
        "mma.sync.aligned.m16n8k32.row.col.s32.s8.s8.s32 "
        "{%0,%1,%2,%3}, {%4,%5,%6,%7}, {%8,%9}, {%0,%1,%2,%3};"
        : "+r"(c[0]), "+r"(c[1]), "+r"(c[2]), "+r"(c[3])
        : "r"(a[0]), "r"(a[1]), "r"(a[2]), "r"(a[3]), "r"(b[0]), "r"(b[1]));
}
static __device__ __forceinline__ uint32_t pack4(float4 v, float s) {
    int q0 = __float2int_rn(v.x * s), q1 = __float2int_rn(v.y * s);
    int q2 = __float2int_rn(v.z * s), q3 = __float2int_rn(v.w * s);
    return (uint32_t)(q0 & 255) | ((uint32_t)(q1 & 255) << 8) |
           ((uint32_t)(q2 & 255) << 16) | ((uint32_t)(q3 & 255) << 24);
}
static __device__ __forceinline__ void decode_tile(int t, int& bi, int& bj) {
    int b = (int)((129.0f - sqrtf(16641.0f - 8.0f * (float)t)) * 0.5f);
    while ((b + 1) * (129 - (b + 1)) / 2 <= t) ++b;
    while (b * (129 - b) / 2 > t) --b;
    bi = b; bj = b + (t - b * (129 - b) / 2);
}

// ---------------------------------------------------------------------------
// Kernel 1: per-row norm + int8 quantization + temperature-folded constants
// + dtype detect + class load + counter/accumulator reset. One warp per row.
// ---------------------------------------------------------------------------
__global__ void prep_kernel(const float* __restrict__ pred,
                            const void* __restrict__ tgt,
                            const float* __restrict__ tempPtr) {
    int warp = (blockIdx.x * blockDim.x + threadIdx.x) >> 5;
    int lane = threadIdx.x & 31;
    if (warp >= N_PTS) return;

    // dtype scan on first 1KB (L2-resident): int32 data shows values >= 64
    const long long* t64 = (const long long*)tgt;
    int bad = 0;
#pragma unroll
    for (int q = 0; q < 4; ++q) {
        long long v = t64[lane + 32 * q];
        bad |= (v < 0 || v >= (long long)NUM_CLS);
    }
    bool is64 = (__ballot_sync(0xffffffffu, bad) == 0u);

    const float4* row = (const float4*)(pred + (size_t)warp * D_DIM);
    float4 v0 = row[lane], v1 = row[lane + 32];
    float s = v0.x * v0.x + v0.y * v0.y + v0.z * v0.z + v0.w * v0.w
            + v1.x * v1.x + v1.y * v1.y + v1.z * v1.z + v1.w * v1.w;
    float m = fmaxf(fmaxf(fmaxf(fabsf(v0.x), fabsf(v0.y)),
                          fmaxf(fabsf(v0.z), fabsf(v0.w))),
                    fmaxf(fmaxf(fabsf(v1.x), fabsf(v1.y)),
                          fmaxf(fabsf(v1.z), fabsf(v1.w))));
#pragma unroll
    for (int o = 16; o; o >>= 1) {
        s += __shfl_xor_sync(0xffffffffu, s, o);
        m = fmaxf(m, __shfl_xor_sync(0xffffffffu, m, o));
    }
    float scale = 127.0f / m;                    // m > 0 for gaussian data
    g_q8[warp * 64 + lane]      = pack4(v0, scale);
    g_q8[warp * 64 + 32 + lane] = pack4(v1, scale);
    if (lane == 0) {
        float invT = 1.0f / tempPtr[0];
        float rs   = m * (1.0f / 127.0f);
        int cls    = is64 ? (int)t64[warp] : ((const int*)tgt)[warp];
        g_aux[warp] = make_float4(-s * invT * LOG2E,
                                  rs * sqrtf(2.0f * invT * LOG2E),
                                  __int_as_float(cls), 0.f);
        g_pos[warp] = 0.f;
        g_neg[warp] = 0.f;
        if (warp == 0) { g_work = 0; g_done = 0; }
    }
}

// ---------------------------------------------------------------------------
// Kernel 2: persistent int8 m16n8k32 Gram tiles with work-stealing; next
// tile prefetch overlaps current epilogue; fused epilogue + folded finalize.
// ---------------------------------------------------------------------------
__global__ __launch_bounds__(256, 2)
void tile_kernel(float* __restrict__ out) {
    extern __shared__ char smc[];
    uint32_t sbase = smem_u32(smc);
    float* bR  = (float*)(smc + AUX_OFF);
    float* bC  = bR + BT;
    float* rkR = bC + BT;
    float* rkC = rkR + BT;
    int*   clR = (int*)(rkC + BT);
    int*   clC = clR + BT;
    __shared__ int s_cur, s_nxt, s_fin;

    int tid  = threadIdx.x;
    int lane = tid & 31, wid = tid >> 5;
    int wm = wid & 1, wn = wid >> 1;              // 2 x 4 warp grid
    int R0 = wm * 64, C0 = wn * 32;
    int gq = lane >> 2, tq = lane & 3;

    // cp.async role: 8 x 16B per chunk (256 rows x 128B)
    int seg = tid & 7;
    int rbase = tid >> 3;

    auto prefetch = [&](int i0, int j0) {
#pragma unroll
        for (int st = 0; st < 2; ++st) {
            uint32_t sdst = sbase + (uint32_t)(st * STAGE_BYTES) + seg * 16u;
            int k0 = st * CE;
#pragma unroll
            for (int i = 0; i < 8; ++i) {
                int row = rbase + 32 * i;         // 0..255
                const char* src = (row < 128)
                    ? (const char*)g_q8 + (size_t)(i0 + row) * D_DIM
                    : (const char*)g_q8 + (size_t)(j0 + row - 128) * D_DIM;
                cp16(sdst + (uint32_t)row * ROWB, src + k0 + seg * 16);
            }
            CP_COMMIT();
        }
    };

    uint32_t offA = (uint32_t)((R0 + (lane & 15)) * ROWB + (lane >> 4) * 16);
    uint32_t offB = (uint32_t)((128 + C0 + (lane >> 4) * 8 + (lane & 7)) * ROWB
                               + ((lane >> 3) & 1) * 16);

    if (tid == 0) s_cur = atomicAdd(&g_work, 1);
    __syncthreads();
    int tile = s_cur, bi = 0, bj = 0;
    if (tile < N_CTAS) {
        decode_tile(tile, bi, bj);
        prefetch(bi * BT, bj * BT);
    }

    while (tile < N_CTAS) {
        int i0 = bi * BT, j0 = bj * BT;
        bool diag = (bi == bj);

        if (tid < BT) {                           // safe: end-of-loop sync
            float4 a = g_aux[i0 + tid];
            bR[tid] = a.x; rkR[tid] = a.y; clR[tid] = __float_as_int(a.z);
            float4 b = g_aux[j0 + tid];
            bC[tid] = b.x; rkC[tid] = b.y; clC[tid] = __float_as_int(b.z);
        }

        int acc[4][4][4];
#pragma unroll
        for (int mi = 0; mi < 4; mi++)
#pragma unroll
            for (int ni = 0; ni < 4; ni++)
#pragma unroll
                for (int v = 0; v < 4; v++) acc[mi][ni][v] = 0;

#pragma unroll
        for (int c = 0; c < 2; ++c) {
            if (c == 0) CP_WAIT(1); else CP_WAIT(0);
            __syncthreads();                      // stage ready + aux visible
            uint32_t sA = sbase + (uint32_t)(c * STAGE_BYTES);
#pragma unroll
            for (int ks = 0; ks < 4; ++ks) {
                uint32_t a[4][4], b[4][2];
#pragma unroll
                for (int mi = 0; mi < 4; mi++)
                    ldsm4(a[mi], sA + offA + (uint32_t)(mi * 16 * ROWB + ks * 32));
#pragma unroll
                for (int p = 0; p < 2; p++) {
                    uint32_t r[4];
                    ldsm4(r, sA + offB + (uint32_t)(p * 16 * ROWB + ks * 32));
                    b[2 * p][0] = r[0]; b[2 * p][1] = r[1];
                    b[2 * p + 1][0] = r[2]; b[2 * p + 1][1] = r[3];
                }
#pragma unroll
                for (int mi = 0; mi < 4; mi++)
#pragma unroll
                    for (int ni = 0; ni < 4; ni++)
                        mma_s8(acc[mi][ni], a[mi], b[ni]);
            }
        }

        // fetch next tile + start its DMA before the epilogue
        if (tid == 0) s_nxt = atomicAdd(&g_work, 1);
        __syncthreads();                          // stages free + s_nxt visible
        int nxt = s_nxt, bi2 = 0, bj2 = 0;
        if (nxt < N_CTAS) {
            decode_tile(nxt, bi2, bj2);
            prefetch(bi2 * BT, bj2 * BT);
        }

        // ---- Epilogue: dv = 2^(acc*rk_i*rk_j + b_i + b_j), masked sums ----
        float bI[8], rkI[8]; int cI[8];
#pragma unroll
        for (int q = 0; q < 8; q++) {
            int rl = R0 + (q >> 1) * 16 + gq + (q & 1) * 8;
            bI[q] = bR[rl]; rkI[q] = rkR[rl]; cI[q] = clR[rl];
        }
        float bJ[8], rkJ[8]; int cJ[8];
#pragma unroll
        for (int q = 0; q < 8; q++) {
            int cl = C0 + (q >> 1) * 8 + tq * 2 + (q & 1);
            bJ[q] = bC[cl]; rkJ[q] = rkC[cl]; cJ[q] = clC[cl];
        }

        float rT[8], rP[8], cT[8], cP[8];
#pragma unroll
        for (int q = 0; q < 8; q++) { rT[q] = rP[q] = cT[q] = cP[q] = 0.f; }

#pragma unroll
        for (int mi = 0; mi < 4; mi++)
#pragma unroll
            for (int h = 0; h < 2; h++) {
                int qr = mi * 2 + h;
                int rl = R0 + mi * 16 + gq + h * 8;
                float bi_ = bI[qr], rki = rkI[qr];
                int ci = cI[qr];
#pragma unroll
                for (int ni = 0; ni < 4; ni++)
#pragma unroll
                    for (int w = 0; w < 2; w++) {
                        int qc = ni * 2 + w;
                        float dotf = (float)acc[mi][ni][h * 2 + w];
                        float dv = exp2f(fmaf(dotf, rki * rkJ[qc], bi_ + bJ[qc]));
                        if (diag && rl == (C0 + ni * 8 + tq * 2 + w)) dv = 0.f;
                        rT[qr] += dv; cT[qc] += dv;
                        if (ci == cJ[qc]) { rP[qr] += dv; cP[qc] += dv; }
                    }
            }

#pragma unroll
        for (int q = 0; q < 8; q++) {
#pragma unroll
            for (int o = 4; o <= 16; o <<= 1) {
                cT[q] += __shfl_xor_sync(0xffffffffu, cT[q], o);
                cP[q] += __shfl_xor_sync(0xffffffffu, cP[q], o);
            }
        }
        if (lane < 4) {
#pragma unroll
            for (int q = 0; q < 8; q++) {
                int cl = C0 + (q >> 1) * 8 + lane * 2 + (q & 1);
                atomicAdd(&g_pos[j0 + cl], cP[q]);
                atomicAdd(&g_neg[j0 + cl], cT[q] - cP[q]);
            }
        }
#pragma unroll
        for (int q = 0; q < 8; q++) {
#pragma unroll
            for (int o = 1; o <= 2; o <<= 1) {
                rT[q] += __shfl_xor_sync(0xffffffffu, rT[q], o);
                rP[q] += __shfl_xor_sync(0xffffffffu, rP[q], o);
            }
        }
        if (!diag && tq == 0) {
#pragma unroll
            for (int q = 0; q < 8; q++) {
                int rl = R0 + (q >> 1) * 16 + gq + (q & 1) * 8;
                atomicAdd(&g_pos[i0 + rl], rP[q]);
                atomicAdd(&g_neg[i0 + rl], rT[q] - rP[q]);
            }
        }

        // tile completion; last tile's CTA runs the final reduction
        if (tid == 0) {
            __threadfence();
            s_fin = (atomicAdd(&g_done, 1) == N_CTAS - 1);
        }
        __syncthreads();                          // also guards aux rewrite
        if (s_fin) {
            __threadfence();
            __shared__ float red[8];
            float s = 0.f;
            for (int j = tid; j < N_PTS; j += 256) {
                float num = g_pos[j];
                float den = fmaxf(g_neg[j], EPSF);
                float frac = num / (num + den);
                if (frac >= EPSF) s += logf(frac);
            }
#pragma unroll
            for (int o = 16; o; o >>= 1) s += __shfl_xor_sync(0xffffffffu, s, o);
            if (lane == 0) red[wid] = s;
            __syncthreads();
            if (tid < 8) {
                float v = red[tid];
#pragma unroll
                for (int o = 4; o; o >>= 1) v += __shfl_xor_sync(0xffu, v, o);
                if (tid == 0) out[0] = -v / (float)N_PTS;
            }
        }

        tile = nxt; bi = bi2; bj = bj2;
    }
}

// ---------------------------------------------------------------------------
extern "C" void kernel_launch(void* const* d_in, const int* in_sizes, int n_in,
                              void* d_out, int out_size) {
    const float* pred = (const float*)d_in[0];
    const void*  tgt  = d_in[1];
    const float* temp = (const float*)d_in[2];

    cudaFuncSetAttribute(tile_kernel,
                         cudaFuncAttributeMaxDynamicSharedMemorySize, SMEM_TOTAL);

    prep_kernel<<<(N_PTS * 32 + 255) / 256, 256>>>(pred, tgt, temp);
    tile_kernel<<<GRID_P, 256, SMEM_TOTAL>>>((float*)d_out);
}